// round 6
// baseline (speedup 1.0000x reference)
#include <cuda_runtime.h>

#define Hh 512
#define Ww 512
#define Bb 8
#define HW (Hh*Ww)

#define TH 16
#define TW 64
#define NT 256
#define CHUNK 4
#define Y1H (TH+2)   // 18
#define Y1W 66       // real cols needed
#define Y1WP 68      // padded stride (16B-aligned rows)
#define XH  (TH+4)   // 20
#define XW  72       // padded halo row
#define WROW 12      // padded per-(cl,co) weight row (9 used)

__global__ __launch_bounds__(NT, 2)
void fused_deform_kernel(const float* __restrict__ x,
                         const float* __restrict__ w1, const float* __restrict__ b1,
                         const float* __restrict__ w2, const float* __restrict__ b2,
                         const float* __restrict__ wd, const float* __restrict__ bd,
                         float* __restrict__ out)
{
    __shared__ __align__(16) float sx[3][XH][XW];            // 17.3 KB
    __shared__ __align__(16) float sy1[CHUNK][Y1H][Y1WP];    // 19.6 KB
    __shared__ __align__(16) float sw2[CHUNK * 18 * WROW];   //  3.5 KB [cl][co][12]
    __shared__ __align__(16) float sw1[64 * 27];             //  6.9 KB
    __shared__ __align__(16) float4 sw1t[27];                // chunk weights [tap][4cl]
    __shared__ float sb1[64];
    __shared__ float swd[81];
    __shared__ float sbd[3];

    const int tid = threadIdx.x;
    const int b   = blockIdx.z;
    const int y0  = blockIdx.y * TH;
    const int x0  = blockIdx.x * TW;

    // ---- stage constants ----
    for (int i = tid; i < 64 * 27; i += NT) sw1[i] = __ldg(&w1[i]);
    if (tid < 64) sb1[tid] = __ldg(&b1[tid]);
    if (tid < 81) swd[tid] = __ldg(&wd[tid]);
    if (tid < 3)  sbd[tid] = __ldg(&bd[tid]);

    // ---- stage x halo (rows y0-2..y0+17, cols x0-2..x0+65, zero padded) ----
    for (int i = tid; i < 3 * XH * XW; i += NT) {
        int c  = i / (XH * XW);
        int rr = (i / XW) % XH;
        int cc = i % XW;
        int gy = y0 - 2 + rr;
        int gx = x0 - 2 + cc;
        float v = 0.f;
        if (gy >= 0 && gy < Hh && gx >= 0 && gx < Ww)
            v = __ldg(&x[(size_t)(b * 3 + c) * HW + gy * Ww + gx]);
        sx[c][rr][cc] = v;
    }

    // ---- per-thread offset accumulators: 4 px x 18 channels ----
    float acc[18][4];
#pragma unroll
    for (int co = 0; co < 18; co++) {
        float bv = __ldg(&b2[co]);
        acc[co][0] = bv; acc[co][1] = bv; acc[co][2] = bv; acc[co][3] = bv;
    }

    const int r     = tid >> 4;        // 0..15 : tile row
    const int cbase = (tid & 15) * 4;  // 0..60 : tile col group

    for (int ch0 = 0; ch0 < 64; ch0 += CHUNK) {
        __syncthreads();  // previous chunk's sy1/sw2/sw1t fully consumed

        // stage conv2 weight chunk: sw2[cl][co][0..8] = w2[co][ch0+cl][tap]
        for (int i = tid; i < CHUNK * 18 * 9; i += NT) {
            int cl = i / (18 * 9);
            int rem = i % (18 * 9);
            int co = rem / 9;
            int t  = rem % 9;
            sw2[(cl * 18 + co) * WROW + t] = __ldg(&w2[co * 576 + (ch0 + cl) * 9 + t]);
        }
        // stage transposed conv1 chunk weights: sw1t[tap] = {cl0,cl1,cl2,cl3}
        if (tid < 108) {
            int t  = tid >> 2;
            int cl = tid & 3;
            ((float*)sw1t)[t * 4 + cl] = sw1[(ch0 + cl) * 27 + t];
        }
        __syncthreads();

        // conv1 (+ReLU, image-masked): one task = 4 channels x 4 px.
        for (int task = tid; task < Y1H * 17; task += NT) {
            int row = task / 17;
            int c0  = (task % 17) * 4;

            float a[4][4];
#pragma unroll
            for (int cl = 0; cl < 4; cl++) {
                float bv = sb1[ch0 + cl];
                a[cl][0] = bv; a[cl][1] = bv; a[cl][2] = bv; a[cl][3] = bv;
            }

#pragma unroll
            for (int c = 0; c < 3; c++) {
                float v[3][6];
#pragma unroll
                for (int dy = 0; dy < 3; dy++) {
                    float4 p4 = *(const float4*)&sx[c][row + dy][c0];
                    float2 p2 = *(const float2*)&sx[c][row + dy][c0 + 4];
                    v[dy][0] = p4.x; v[dy][1] = p4.y;
                    v[dy][2] = p4.z; v[dy][3] = p4.w;
                    v[dy][4] = p2.x; v[dy][5] = p2.y;
                }
#pragma unroll
                for (int t9 = 0; t9 < 9; t9++) {
                    const int dy = t9 / 3, dx = t9 % 3;
                    float4 w4 = sw1t[c * 9 + t9];
#pragma unroll
                    for (int j = 0; j < 4; j++) {
                        float vv = v[dy][dx + j];
                        a[0][j] = fmaf(vv, w4.x, a[0][j]);
                        a[1][j] = fmaf(vv, w4.y, a[1][j]);
                        a[2][j] = fmaf(vv, w4.z, a[2][j]);
                        a[3][j] = fmaf(vv, w4.w, a[3][j]);
                    }
                }
            }

            int gyy = y0 - 1 + row;
            bool okY = (gyy >= 0) && (gyy < Hh);
            bool okJ[4];
#pragma unroll
            for (int j = 0; j < 4; j++) {
                int col = c0 + j;
                int gx  = x0 - 1 + col;
                okJ[j] = okY && (col < Y1W) && (gx >= 0) && (gx < Ww);
            }
#pragma unroll
            for (int cl = 0; cl < 4; cl++) {
                float4 rv;
                rv.x = okJ[0] ? fmaxf(a[cl][0], 0.f) : 0.f;
                rv.y = okJ[1] ? fmaxf(a[cl][1], 0.f) : 0.f;
                rv.z = okJ[2] ? fmaxf(a[cl][2], 0.f) : 0.f;
                rv.w = okJ[3] ? fmaxf(a[cl][3], 0.f) : 0.f;
                *(float4*)&sy1[cl][row][c0] = rv;
            }
        }
        __syncthreads();

        // conv2 accumulate, co-outer: per (cl,co): 3 LDS (w[9]) + 36 FMA.
        // Hot live set: acc 72 + n 18 + w 9 -> fits 128 regs.
#pragma unroll 1
        for (int cl = 0; cl < CHUNK; cl++) {
            float n[3][6];
#pragma unroll
            for (int r2 = 0; r2 < 3; r2++) {
                float4 p4 = *(const float4*)&sy1[cl][r + r2][cbase];
                float2 p2 = *(const float2*)&sy1[cl][r + r2][cbase + 4];
                n[r2][0] = p4.x; n[r2][1] = p4.y; n[r2][2] = p4.z;
                n[r2][3] = p4.w; n[r2][4] = p2.x; n[r2][5] = p2.y;
            }
#pragma unroll
            for (int co = 0; co < 18; co++) {
                const float* wp = &sw2[(cl * 18 + co) * WROW];
                float4 wa = *(const float4*)(wp);
                float4 wb = *(const float4*)(wp + 4);
                float  wc = wp[8];
                float w[9];
                w[0] = wa.x; w[1] = wa.y; w[2] = wa.z; w[3] = wa.w;
                w[4] = wb.x; w[5] = wb.y; w[6] = wb.z; w[7] = wb.w;
                w[8] = wc;
#pragma unroll
                for (int t = 0; t < 9; t++) {
                    const int ky = t / 3, kx = t % 3;
                    acc[co][0] = fmaf(n[ky][kx + 0], w[t], acc[co][0]);
                    acc[co][1] = fmaf(n[ky][kx + 1], w[t], acc[co][1]);
                    acc[co][2] = fmaf(n[ky][kx + 2], w[t], acc[co][2]);
                    acc[co][3] = fmaf(n[ky][kx + 3], w[t], acc[co][3]);
                }
            }
        }
    }

    // ---- deformable conv epilogue: offsets live in acc ----
    const int gy = y0 + r;
    const float* xb = x + (size_t)(b * 3) * HW;
    float o[3][4];
#pragma unroll
    for (int j = 0; j < 4; j++) {
        int gx = x0 + cbase + j;
        float a0 = sbd[0], a1 = sbd[1], a2 = sbd[2];
#pragma unroll
        for (int k = 0; k < 9; k++) {
            float dy = acc[2 * k][j];
            float dx = acc[2 * k + 1][j];
            float ys = (float)(gy + k / 3 - 1) + dy;
            float xs = (float)(gx + k % 3 - 1) + dx;
            float yf = floorf(ys), xf = floorf(xs);
            int iy0 = (int)yf, ix0 = (int)xf;
            float fy = ys - yf, fx = xs - xf;
            float s0 = 0.f, s1 = 0.f, s2 = 0.f;
#pragma unroll
            for (int cy = 0; cy < 2; cy++)
#pragma unroll
                for (int cx = 0; cx < 2; cx++) {
                    int iy = iy0 + cy, ix = ix0 + cx;
                    float wgt = (cy ? fy : 1.f - fy) * (cx ? fx : 1.f - fx);
                    bool ok = (iy >= 0) && (iy < Hh) && (ix >= 0) && (ix < Ww);
                    wgt = ok ? wgt : 0.f;
                    int idx = min(max(iy, 0), Hh - 1) * Ww + min(max(ix, 0), Ww - 1);
                    s0 = fmaf(wgt, __ldg(xb + idx), s0);
                    s1 = fmaf(wgt, __ldg(xb + HW + idx), s1);
                    s2 = fmaf(wgt, __ldg(xb + 2 * HW + idx), s2);
                }
            a0 = fmaf(s0, swd[ 0 + k], fmaf(s1, swd[ 9 + k], fmaf(s2, swd[18 + k], a0)));
            a1 = fmaf(s0, swd[27 + k], fmaf(s1, swd[36 + k], fmaf(s2, swd[45 + k], a1)));
            a2 = fmaf(s0, swd[54 + k], fmaf(s1, swd[63 + k], fmaf(s2, swd[72 + k], a2)));
        }
        o[0][j] = a0; o[1][j] = a1; o[2][j] = a2;
    }
#pragma unroll
    for (int c = 0; c < 3; c++) {
        float4 v;
        v.x = o[c][0]; v.y = o[c][1]; v.z = o[c][2]; v.w = o[c][3];
        *(float4*)&out[(size_t)(b * 3 + c) * HW + (size_t)gy * Ww + x0 + cbase] = v;
    }
}

extern "C" void kernel_launch(void* const* d_in, const int* in_sizes, int n_in,
                              void* d_out, int out_size)
{
    const float* x  = (const float*)d_in[0];
    const float* w1 = (const float*)d_in[1];
    const float* b1 = (const float*)d_in[2];
    const float* w2 = (const float*)d_in[3];
    const float* b2 = (const float*)d_in[4];
    const float* wd = (const float*)d_in[5];
    const float* bd = (const float*)d_in[6];
    float* out = (float*)d_out;

    dim3 grid(Ww / TW, Hh / TH, Bb);   // 8 x 32 x 8 = 2048 blocks
    fused_deform_kernel<<<grid, NT>>>(x, w1, b1, w2, b2, wd, bd, out);
}

// round 8
// speedup vs baseline: 1.3526x; 1.3526x over previous
#include <cuda_runtime.h>

#define Hh 512
#define Ww 512
#define Bb 8
#define HW (Hh*Ww)

#define TH 16
#define TW 64
#define NT 512
#define CHUNK 4
#define Y1H (TH+2)   // 18
#define Y1W 66       // real cols needed
#define Y1WP 68      // padded stride (16B-aligned rows)
#define XH  (TH+4)   // 20
#define XW  72       // padded halo row
#define WROW 12      // padded per-(cl,co) weight row (9 used)

#define SX_FLOATS (3 * XH * XW)             // 4320
#define SY1_FLOATS (CHUNK * Y1H * Y1WP)     // 4896
#define BIG_FLOATS (SX_FLOATS + SY1_FLOATS) // 9216 floats = 36864 B (== soff size)

__global__ __launch_bounds__(NT, 1)
void fused_deform_kernel(const float* __restrict__ x,
                         const float* __restrict__ w1, const float* __restrict__ b1,
                         const float* __restrict__ w2, const float* __restrict__ b2,
                         const float* __restrict__ wd, const float* __restrict__ bd,
                         float* __restrict__ out)
{
    // Big buffer aliases: [conv phase] sx + sy1   |   [epilogue] soff[512][18]
    __shared__ __align__(16) float smem_big[BIG_FLOATS];     // 36.9 KB
    __shared__ __align__(16) float sw2[CHUNK * 18 * WROW];   //  3.5 KB [cl][co][12]
    __shared__ __align__(16) float sw1[64 * 27];             //  6.9 KB
    __shared__ __align__(16) float4 sw1t[27];                // chunk w [tap][4cl]
    __shared__ float sb1[64];
    __shared__ float swd[81];
    __shared__ float sbd[3];

    float (*sx)[XH][XW]     = (float (*)[XH][XW])smem_big;
    float (*sy1)[Y1H][Y1WP] = (float (*)[Y1H][Y1WP])(smem_big + SX_FLOATS);
    float (*soff)[18]       = (float (*)[18])smem_big;

    const int tid  = threadIdx.x;
    const int half = tid >> 8;          // 0/1 : which 9 output channels
    const int grp  = tid & 255;         // pixel group id
    const int b    = blockIdx.z;
    const int y0   = blockIdx.y * TH;
    const int x0   = blockIdx.x * TW;
    const int coBase = half * 9;

    // ---- stage constants ----
    for (int i = tid; i < 64 * 27; i += NT) sw1[i] = __ldg(&w1[i]);
    if (tid < 64) sb1[tid] = __ldg(&b1[tid]);
    if (tid < 81) swd[tid] = __ldg(&wd[tid]);
    if (tid < 3)  sbd[tid] = __ldg(&bd[tid]);

    // ---- stage x halo (rows y0-2..y0+17, cols x0-2..x0+65, zero padded) ----
    for (int i = tid; i < SX_FLOATS; i += NT) {
        int c  = i / (XH * XW);
        int rr = (i / XW) % XH;
        int cc = i % XW;
        int gy = y0 - 2 + rr;
        int gx = x0 - 2 + cc;
        float v = 0.f;
        if (gy >= 0 && gy < Hh && gx >= 0 && gx < Ww)
            v = __ldg(&x[(size_t)(b * 3 + c) * HW + gy * Ww + gx]);
        sx[c][rr][cc] = v;
    }

    // ---- per-thread offset accumulators: 4 px x 9 channels ----
    float acc[9][4];
#pragma unroll
    for (int c9 = 0; c9 < 9; c9++) {
        float bv = __ldg(&b2[coBase + c9]);
        acc[c9][0] = bv; acc[c9][1] = bv; acc[c9][2] = bv; acc[c9][3] = bv;
    }

    const int r     = grp >> 4;        // 0..15 : tile row
    const int cbase = (grp & 15) * 4;  // 0..60 : tile col group

    for (int ch0 = 0; ch0 < 64; ch0 += CHUNK) {
        __syncthreads();  // previous chunk's sy1/sw2/sw1t fully consumed

        // stage conv2 weight chunk: sw2[cl][co][t] = w2[co][ch0+cl][t]
        for (int i = tid; i < CHUNK * 18 * 9; i += NT) {
            int cl  = i / (18 * 9);
            int rem = i % (18 * 9);
            int co  = rem / 9;
            int t   = rem % 9;
            sw2[(cl * 18 + co) * WROW + t] = __ldg(&w2[co * 576 + (ch0 + cl) * 9 + t]);
        }
        // stage transposed conv1 chunk weights: sw1t[tap] = {cl0,cl1,cl2,cl3}
        if (tid < 108) {
            int t  = tid >> 2;
            int cl = tid & 3;
            ((float*)sw1t)[t * 4 + cl] = sw1[(ch0 + cl) * 27 + t];
        }
        __syncthreads();

        // conv1 (+ReLU, image-masked): one task = 4 channels x 4 px. 306 tasks, 1 pass.
        if (tid < Y1H * 17) {
            int row = tid / 17;
            int c0  = (tid % 17) * 4;

            float a[4][4];
#pragma unroll
            for (int cl = 0; cl < 4; cl++) {
                float bv = sb1[ch0 + cl];
                a[cl][0] = bv; a[cl][1] = bv; a[cl][2] = bv; a[cl][3] = bv;
            }

#pragma unroll
            for (int c = 0; c < 3; c++) {
                float v[3][6];
#pragma unroll
                for (int dy = 0; dy < 3; dy++) {
                    float4 p4 = *(const float4*)&sx[c][row + dy][c0];
                    float2 p2 = *(const float2*)&sx[c][row + dy][c0 + 4];
                    v[dy][0] = p4.x; v[dy][1] = p4.y;
                    v[dy][2] = p4.z; v[dy][3] = p4.w;
                    v[dy][4] = p2.x; v[dy][5] = p2.y;
                }
#pragma unroll
                for (int t9 = 0; t9 < 9; t9++) {
                    const int dy = t9 / 3, dx = t9 % 3;
                    float4 w4 = sw1t[c * 9 + t9];
#pragma unroll
                    for (int j = 0; j < 4; j++) {
                        float vv = v[dy][dx + j];
                        a[0][j] = fmaf(vv, w4.x, a[0][j]);
                        a[1][j] = fmaf(vv, w4.y, a[1][j]);
                        a[2][j] = fmaf(vv, w4.z, a[2][j]);
                        a[3][j] = fmaf(vv, w4.w, a[3][j]);
                    }
                }
            }

            int gyy = y0 - 1 + row;
            bool okY = (gyy >= 0) && (gyy < Hh);
            bool okJ[4];
#pragma unroll
            for (int j = 0; j < 4; j++) {
                int col = c0 + j;
                int gx  = x0 - 1 + col;
                okJ[j] = okY && (col < Y1W) && (gx >= 0) && (gx < Ww);
            }
#pragma unroll
            for (int cl = 0; cl < 4; cl++) {
                float4 rv;
                rv.x = okJ[0] ? fmaxf(a[cl][0], 0.f) : 0.f;
                rv.y = okJ[1] ? fmaxf(a[cl][1], 0.f) : 0.f;
                rv.z = okJ[2] ? fmaxf(a[cl][2], 0.f) : 0.f;
                rv.w = okJ[3] ? fmaxf(a[cl][3], 0.f) : 0.f;
                *(float4*)&sy1[cl][row][c0] = rv;
            }
        }
        __syncthreads();

        // conv2 accumulate (this thread's 9 channels): per (cl,c9): 3 LDS + 36 FMA
#pragma unroll 1
        for (int cl = 0; cl < CHUNK; cl++) {
            float n[3][6];
#pragma unroll
            for (int r2 = 0; r2 < 3; r2++) {
                float4 p4 = *(const float4*)&sy1[cl][r + r2][cbase];
                float2 p2 = *(const float2*)&sy1[cl][r + r2][cbase + 4];
                n[r2][0] = p4.x; n[r2][1] = p4.y; n[r2][2] = p4.z;
                n[r2][3] = p4.w; n[r2][4] = p2.x; n[r2][5] = p2.y;
            }
#pragma unroll
            for (int c9 = 0; c9 < 9; c9++) {
                const float* wp = &sw2[(cl * 18 + coBase + c9) * WROW];
                float4 wa = *(const float4*)(wp);
                float4 wb = *(const float4*)(wp + 4);
                float  w8 = wp[8];
                float w[9];
                w[0] = wa.x; w[1] = wa.y; w[2] = wa.z; w[3] = wa.w;
                w[4] = wb.x; w[5] = wb.y; w[6] = wb.z; w[7] = wb.w;
                w[8] = w8;
#pragma unroll
                for (int t = 0; t < 9; t++) {
                    const int ky = t / 3, kx = t % 3;
                    acc[c9][0] = fmaf(n[ky][kx + 0], w[t], acc[c9][0]);
                    acc[c9][1] = fmaf(n[ky][kx + 1], w[t], acc[c9][1]);
                    acc[c9][2] = fmaf(n[ky][kx + 2], w[t], acc[c9][2]);
                    acc[c9][3] = fmaf(n[ky][kx + 3], w[t], acc[c9][3]);
                }
            }
        }
    }

    // ---- exchange: give partner its missing 9 channels for its 2 pixels ----
    __syncthreads();   // all conv reads of smem_big complete; safe to alias
    {
        const int pj = 2 * (1 - half);    // pixels the partner will process
#pragma unroll
        for (int c9 = 0; c9 < 9; c9++) {
            soff[tid][c9 * 2 + 0] = acc[c9][pj + 0];
            soff[tid][c9 * 2 + 1] = acc[c9][pj + 1];
        }
    }
    __syncthreads();

    // ---- build full 18-channel offsets for this thread's 2 pixels ----
    float off[18][2];
    {
        const float* pp = soff[tid ^ 256];
        const int mj = 2 * half;
#pragma unroll
        for (int c9 = 0; c9 < 9; c9++) {
            off[coBase + c9][0] = acc[c9][mj + 0];
            off[coBase + c9][1] = acc[c9][mj + 1];
            off[(9 - coBase) + c9][0] = pp[c9 * 2 + 0];
            off[(9 - coBase) + c9][1] = pp[c9 * 2 + 1];
        }
    }

    // ---- deformable conv epilogue: 2 pixels per thread ----
    const int gy = y0 + r;
    const int gx0 = x0 + cbase + 2 * half;
    const float* xb = x + (size_t)(b * 3) * HW;
    float o[3][2];
#pragma unroll
    for (int j = 0; j < 2; j++) {
        int gx = gx0 + j;
        float a0 = sbd[0], a1 = sbd[1], a2 = sbd[2];
#pragma unroll
        for (int k = 0; k < 9; k++) {
            float dy = off[2 * k][j];
            float dx = off[2 * k + 1][j];
            float ys = (float)(gy + k / 3 - 1) + dy;
            float xs = (float)(gx + k % 3 - 1) + dx;
            float yf = floorf(ys), xf = floorf(xs);
            int iy0 = (int)yf, ix0 = (int)xf;
            float fy = ys - yf, fx = xs - xf;
            float s0 = 0.f, s1 = 0.f, s2 = 0.f;
#pragma unroll
            for (int cy = 0; cy < 2; cy++)
#pragma unroll
                for (int cx = 0; cx < 2; cx++) {
                    int iy = iy0 + cy, ix = ix0 + cx;
                    float wgt = (cy ? fy : 1.f - fy) * (cx ? fx : 1.f - fx);
                    bool ok = (iy >= 0) && (iy < Hh) && (ix >= 0) && (ix < Ww);
                    wgt = ok ? wgt : 0.f;
                    int idx = min(max(iy, 0), Hh - 1) * Ww + min(max(ix, 0), Ww - 1);
                    s0 = fmaf(wgt, __ldg(xb + idx), s0);
                    s1 = fmaf(wgt, __ldg(xb + HW + idx), s1);
                    s2 = fmaf(wgt, __ldg(xb + 2 * HW + idx), s2);
                }
            a0 = fmaf(s0, swd[ 0 + k], fmaf(s1, swd[ 9 + k], fmaf(s2, swd[18 + k], a0)));
            a1 = fmaf(s0, swd[27 + k], fmaf(s1, swd[36 + k], fmaf(s2, swd[45 + k], a1)));
            a2 = fmaf(s0, swd[54 + k], fmaf(s1, swd[63 + k], fmaf(s2, swd[72 + k], a2)));
        }
        o[0][j] = a0; o[1][j] = a1; o[2][j] = a2;
    }
#pragma unroll
    for (int c = 0; c < 3; c++) {
        float2 v;
        v.x = o[c][0]; v.y = o[c][1];
        *(float2*)&out[(size_t)(b * 3 + c) * HW + (size_t)gy * Ww + gx0] = v;
    }
}

extern "C" void kernel_launch(void* const* d_in, const int* in_sizes, int n_in,
                              void* d_out, int out_size)
{
    const float* x  = (const float*)d_in[0];
    const float* w1 = (const float*)d_in[1];
    const float* b1 = (const float*)d_in[2];
    const float* w2 = (const float*)d_in[3];
    const float* b2 = (const float*)d_in[4];
    const float* wd = (const float*)d_in[5];
    const float* bd = (const float*)d_in[6];
    float* out = (float*)d_out;

    dim3 grid(Ww / TW, Hh / TH, Bb);   // 8 x 32 x 8 = 2048 blocks
    fused_deform_kernel<<<grid, NT>>>(x, w1, b1, w2, b2, wd, bd, out);
}

// round 9
// speedup vs baseline: 1.6937x; 1.2522x over previous
#include <cuda_runtime.h>

#define Hh 512
#define Ww 512
#define Bb 8
#define HW (Hh*Ww)

#define TH 16
#define TW 64
#define NT 256
#define CHUNK 8
#define Y1H (TH+2)   // 18
#define Y1W 66       // real cols needed
#define Y1WP 68      // padded stride (16B-aligned rows)
#define XH  (TH+4)   // 20
#define XW  72       // padded halo row
#define WP  20       // padded stride for 18 conv2 output channels

// Dynamic smem layout (floats)
#define OFF_SX   0
#define SX_F     (3 * XH * XW)                 // 4320
#define OFF_SY1  (OFF_SX + SX_F)
#define SY1_F    (CHUNK * Y1H * Y1WP)          // 9792
#define OFF_SW2  (OFF_SY1 + SY1_F)
#define SW2_F    (CHUNK * 9 * WP)              // 1440
#define OFF_SW1  (OFF_SW2 + SW2_F)
#define SW1_F    (64 * 27)                     // 1728
#define OFF_SW1T (OFF_SW1 + SW1_F)
#define SW1T_F   (2 * 27 * 4)                  // 216
#define OFF_SB1  (OFF_SW1T + SW1T_F)
#define OFF_SWD  (OFF_SB1 + 64)
#define OFF_SBD  (OFF_SWD + 81)
#define SMEM_F   (OFF_SBD + 4)
#define SMEM_BYTES (SMEM_F * 4)                // ~70.6 KB

__global__ __launch_bounds__(NT, 1)
void fused_deform_kernel(const float* __restrict__ x,
                         const float* __restrict__ w1, const float* __restrict__ b1,
                         const float* __restrict__ w2, const float* __restrict__ b2,
                         const float* __restrict__ wd, const float* __restrict__ bd,
                         float* __restrict__ out)
{
    extern __shared__ __align__(16) float sm[];
    float (*sx)[XH][XW]     = (float (*)[XH][XW])(sm + OFF_SX);
    float (*sy1)[Y1H][Y1WP] = (float (*)[Y1H][Y1WP])(sm + OFF_SY1);
    float* sw2  = sm + OFF_SW2;                 // [cl][tap][co pad WP]
    float* sw1  = sm + OFF_SW1;
    float4* sw1t = (float4*)(sm + OFF_SW1T);    // [sub][tap] -> {cl0..cl3}
    float* sb1  = sm + OFF_SB1;
    float* swd  = sm + OFF_SWD;
    float* sbd  = sm + OFF_SBD;

    const int tid = threadIdx.x;
    const int b   = blockIdx.z;
    const int y0  = blockIdx.y * TH;
    const int x0  = blockIdx.x * TW;

    // ---- stage constants ----
    for (int i = tid; i < 64 * 27; i += NT) sw1[i] = __ldg(&w1[i]);
    if (tid < 64) sb1[tid] = __ldg(&b1[tid]);
    if (tid < 81) swd[tid] = __ldg(&wd[tid]);
    if (tid < 3)  sbd[tid] = __ldg(&bd[tid]);

    // ---- stage x halo (rows y0-2..y0+17, cols x0-2..x0+65, zero padded) ----
    for (int i = tid; i < SX_F; i += NT) {
        int c  = i / (XH * XW);
        int rr = (i / XW) % XH;
        int cc = i % XW;
        int gy = y0 - 2 + rr;
        int gx = x0 - 2 + cc;
        float v = 0.f;
        if (gy >= 0 && gy < Hh && gx >= 0 && gx < Ww)
            v = __ldg(&x[(size_t)(b * 3 + c) * HW + gy * Ww + gx]);
        sx[c][rr][cc] = v;
    }

    // ---- per-thread offset accumulators: 4 px x 18 channels ----
    float acc[18][4];
#pragma unroll
    for (int co = 0; co < 18; co++) {
        float bv = __ldg(&b2[co]);
        acc[co][0] = bv; acc[co][1] = bv; acc[co][2] = bv; acc[co][3] = bv;
    }

    const int r     = tid >> 4;        // 0..15 : tile row
    const int cbase = (tid & 15) * 4;  // 0..60 : tile col group

    for (int ch0 = 0; ch0 < 64; ch0 += CHUNK) {
        __syncthreads();  // previous chunk's sy1/sw2/sw1t fully consumed

        // stage transposed conv2 weight chunk: sw2[cl*9+t][co] = w2[co][ch0+cl][t]
        for (int i = tid; i < 18 * CHUNK * 9; i += NT) {
            int co = i / (CHUNK * 9);
            int rr = i % (CHUNK * 9);        // cl*9 + tap
            sw2[rr * WP + co] = __ldg(&w2[co * 576 + ch0 * 9 + rr]);
        }
        // stage transposed conv1 chunk weights: sw1t[sub*27+t] = {cl0..cl3}
        if (tid < 216) {
            int sub = tid / 108;
            int rem = tid % 108;
            int t  = rem >> 2;
            int cl = rem & 3;
            ((float*)sw1t)[(sub * 27 + t) * 4 + cl] = sw1[(ch0 + sub * 4 + cl) * 27 + t];
        }
        __syncthreads();

        // conv1 (+ReLU, image-masked): task = 4 channels x 4 px; 612 tasks.
        for (int t2 = tid; t2 < 2 * Y1H * 17; t2 += NT) {
            int sub  = t2 / (Y1H * 17);       // which 4-channel group
            int task = t2 % (Y1H * 17);
            int row = task / 17;
            int c0  = (task % 17) * 4;

            float a[4][4];
#pragma unroll
            for (int cl = 0; cl < 4; cl++) {
                float bv = sb1[ch0 + sub * 4 + cl];
                a[cl][0] = bv; a[cl][1] = bv; a[cl][2] = bv; a[cl][3] = bv;
            }

#pragma unroll
            for (int c = 0; c < 3; c++) {
                float v[3][6];
#pragma unroll
                for (int dy = 0; dy < 3; dy++) {
                    float4 p4 = *(const float4*)&sx[c][row + dy][c0];
                    float2 p2 = *(const float2*)&sx[c][row + dy][c0 + 4];
                    v[dy][0] = p4.x; v[dy][1] = p4.y;
                    v[dy][2] = p4.z; v[dy][3] = p4.w;
                    v[dy][4] = p2.x; v[dy][5] = p2.y;
                }
#pragma unroll
                for (int t9 = 0; t9 < 9; t9++) {
                    const int dy = t9 / 3, dx = t9 % 3;
                    float4 w4 = sw1t[sub * 27 + c * 9 + t9];
#pragma unroll
                    for (int j = 0; j < 4; j++) {
                        float vv = v[dy][dx + j];
                        a[0][j] = fmaf(vv, w4.x, a[0][j]);
                        a[1][j] = fmaf(vv, w4.y, a[1][j]);
                        a[2][j] = fmaf(vv, w4.z, a[2][j]);
                        a[3][j] = fmaf(vv, w4.w, a[3][j]);
                    }
                }
            }

            int gyy = y0 - 1 + row;
            bool okY = (gyy >= 0) && (gyy < Hh);
            bool okJ[4];
#pragma unroll
            for (int j = 0; j < 4; j++) {
                int col = c0 + j;
                int gx  = x0 - 1 + col;
                okJ[j] = okY && (col < Y1W) && (gx >= 0) && (gx < Ww);
            }
#pragma unroll
            for (int cl = 0; cl < 4; cl++) {
                float4 rv;
                rv.x = okJ[0] ? fmaxf(a[cl][0], 0.f) : 0.f;
                rv.y = okJ[1] ? fmaxf(a[cl][1], 0.f) : 0.f;
                rv.z = okJ[2] ? fmaxf(a[cl][2], 0.f) : 0.f;
                rv.w = okJ[3] ? fmaxf(a[cl][3], 0.f) : 0.f;
                *(float4*)&sy1[sub * 4 + cl][row][c0] = rv;
            }
        }
        __syncthreads();

        // conv2 accumulate: 8 cin x 9 taps x 18 co x 4 px
#pragma unroll 1
        for (int cl = 0; cl < CHUNK; cl++) {
            float n[3][6];
#pragma unroll
            for (int r2 = 0; r2 < 3; r2++) {
                float4 p4 = *(const float4*)&sy1[cl][r + r2][cbase];
                float2 p2 = *(const float2*)&sy1[cl][r + r2][cbase + 4];
                n[r2][0] = p4.x; n[r2][1] = p4.y; n[r2][2] = p4.z;
                n[r2][3] = p4.w; n[r2][4] = p2.x; n[r2][5] = p2.y;
            }
#pragma unroll
            for (int t = 0; t < 9; t++) {
                const int ky = t / 3, kx = t % 3;
                const float* wp = &sw2[(cl * 9 + t) * WP];
                float w[18];
#pragma unroll
                for (int q = 0; q < 4; q++) {
                    float4 w4 = *(const float4*)(wp + 4 * q);
                    w[4*q] = w4.x; w[4*q+1] = w4.y; w[4*q+2] = w4.z; w[4*q+3] = w4.w;
                }
                float2 w2v = *(const float2*)(wp + 16);
                w[16] = w2v.x; w[17] = w2v.y;
#pragma unroll
                for (int co = 0; co < 18; co++) {
                    acc[co][0] = fmaf(n[ky][kx + 0], w[co], acc[co][0]);
                    acc[co][1] = fmaf(n[ky][kx + 1], w[co], acc[co][1]);
                    acc[co][2] = fmaf(n[ky][kx + 2], w[co], acc[co][2]);
                    acc[co][3] = fmaf(n[ky][kx + 3], w[co], acc[co][3]);
                }
            }
        }
    }

    // ---- deformable conv epilogue: offsets live in acc ----
    const int gy = y0 + r;
    const float* xb = x + (size_t)(b * 3) * HW;
    float o[3][4];
#pragma unroll
    for (int j = 0; j < 4; j++) {
        int gx = x0 + cbase + j;
        float a0 = sbd[0], a1 = sbd[1], a2 = sbd[2];
#pragma unroll
        for (int k = 0; k < 9; k++) {
            float dy = acc[2 * k][j];
            float dx = acc[2 * k + 1][j];
            float ys = (float)(gy + k / 3 - 1) + dy;
            float xs = (float)(gx + k % 3 - 1) + dx;
            float yf = floorf(ys), xf = floorf(xs);
            int iy0 = (int)yf, ix0 = (int)xf;
            float fy = ys - yf, fx = xs - xf;
            float s0 = 0.f, s1 = 0.f, s2 = 0.f;
#pragma unroll
            for (int cy = 0; cy < 2; cy++)
#pragma unroll
                for (int cx = 0; cx < 2; cx++) {
                    int iy = iy0 + cy, ix = ix0 + cx;
                    float wgt = (cy ? fy : 1.f - fy) * (cx ? fx : 1.f - fx);
                    bool ok = (iy >= 0) && (iy < Hh) && (ix >= 0) && (ix < Ww);
                    wgt = ok ? wgt : 0.f;
                    int idx = min(max(iy, 0), Hh - 1) * Ww + min(max(ix, 0), Ww - 1);
                    s0 = fmaf(wgt, __ldg(xb + idx), s0);
                    s1 = fmaf(wgt, __ldg(xb + HW + idx), s1);
                    s2 = fmaf(wgt, __ldg(xb + 2 * HW + idx), s2);
                }
            a0 = fmaf(s0, swd[ 0 + k], fmaf(s1, swd[ 9 + k], fmaf(s2, swd[18 + k], a0)));
            a1 = fmaf(s0, swd[27 + k], fmaf(s1, swd[36 + k], fmaf(s2, swd[45 + k], a1)));
            a2 = fmaf(s0, swd[54 + k], fmaf(s1, swd[63 + k], fmaf(s2, swd[72 + k], a2)));
        }
        o[0][j] = a0; o[1][j] = a1; o[2][j] = a2;
    }
#pragma unroll
    for (int c = 0; c < 3; c++) {
        float4 v;
        v.x = o[c][0]; v.y = o[c][1]; v.z = o[c][2]; v.w = o[c][3];
        *(float4*)&out[(size_t)(b * 3 + c) * HW + (size_t)gy * Ww + x0 + cbase] = v;
    }
}

extern "C" void kernel_launch(void* const* d_in, const int* in_sizes, int n_in,
                              void* d_out, int out_size)
{
    const float* x  = (const float*)d_in[0];
    const float* w1 = (const float*)d_in[1];
    const float* b1 = (const float*)d_in[2];
    const float* w2 = (const float*)d_in[3];
    const float* b2 = (const float*)d_in[4];
    const float* wd = (const float*)d_in[5];
    const float* bd = (const float*)d_in[6];
    float* out = (float*)d_out;

    cudaFuncSetAttribute(fused_deform_kernel,
                         cudaFuncAttributeMaxDynamicSharedMemorySize, SMEM_BYTES);

    dim3 grid(Ww / TW, Hh / TH, Bb);   // 8 x 32 x 8 = 2048 blocks
    fused_deform_kernel<<<grid, NT, SMEM_BYTES>>>(x, w1, b1, w2, b2, wd, bd, out);
}